// round 17
// baseline (speedup 1.0000x reference)
#include <cuda_runtime.h>
#include <cuda_bf16.h>
#include <cstdint>

// ---------------------------------------------------------------------------
// LSTMPointerNet: BS=16, NMEM=256, NQ=63 (T=64), D=512, H=512
// Output: score [16,64,256] f32
//
// R17: (a) LSTM dot -> 4x4 register tile from smem, k interleaved kc*4+q*64
// (conflict-free, 1 load : 4 FMA2), kc-reduction via 16-lane f32x2 butterfly
// shuffle; staging/tail unchanged. (b) GEMMs -> 256-thread blocks, 128x128
// tile (bit-identical C, 2x warps/SM). Score/prep unchanged from R16.
// ---------------------------------------------------------------------------

__device__ float g_xcat[1024 * 512];    // [t*16+b][d]
__device__ float g_wihT[512 * 2048];    // w_ih^T  [d][4H]
__device__ float g_xg  [1024 * 2048];   // [t*16+b][4H]  x @ w_ih^T (no bias)
__device__ float g_feat[4096 * 512];    // [b*256+m][h]
__device__ float g_ys  [1024 * 512];    // [b*64+t][h]
__device__ float g_q   [1024 * 512];    // [b*64+t][h]
__device__ float g_h   [2 * 512 * 16];  // double-buffered h, [buf][k][b]
__device__ float g_c   [512 * 16];      // cell state, [k][b]

// ---------------- helpers ---------------------------------------------------

__device__ __forceinline__ void fma2(unsigned long long& d,
                                     unsigned long long a,
                                     unsigned long long b) {
    asm("fma.rn.f32x2 %0, %1, %2, %0;" : "+l"(d) : "l"(a), "l"(b));
}
__device__ __forceinline__ unsigned long long add2(unsigned long long a,
                                                   unsigned long long b) {
    unsigned long long r;
    asm("add.rn.f32x2 %0, %1, %2;" : "=l"(r) : "l"(a), "l"(b));
    return r;
}
__device__ __forceinline__ unsigned long long pk2(float x) {
    unsigned long long r;
    asm("mov.b64 %0, {%1, %1};" : "=l"(r) : "f"(x));
    return r;
}
__device__ __forceinline__ void unpk(unsigned long long v, float& lo, float& hi) {
    asm("mov.b64 {%0, %1}, %2;" : "=f"(lo), "=f"(hi) : "l"(v));
}
__device__ __forceinline__ float upsum(unsigned long long v) {
    float lo, hi; unpk(v, lo, hi); return lo + hi;
}
__device__ __forceinline__ float4 ldcg4(const float* p) {
    float4 v;
    asm volatile("ld.global.cg.v4.f32 {%0,%1,%2,%3}, [%4];"
                 : "=f"(v.x), "=f"(v.y), "=f"(v.z), "=f"(v.w) : "l"(p));
    return v;
}
__device__ __forceinline__ float rcp_approx(float x) {
    float r;
    asm("rcp.approx.f32 %0, %1;" : "=f"(r) : "f"(x));
    return r;
}
// hw tanh: 1 MUFU (score stage only)
__device__ __forceinline__ float tanh_hw(float x) {
    float r;
    asm("tanh.approx.f32 %0, %1;" : "=f"(r) : "f"(x));
    return r;
}
// rational poly tanh (cell tail; validated)
__device__ __forceinline__ float tanh_poly(float x) {
    const float kClamp = 7.90531110763549805f;
    float xc = fminf(fmaxf(x, -kClamp), kClamp);
    float x2 = xc * xc;
    float p = fmaf(x2, -2.76076847742355e-16f, 2.00018790482477e-13f);
    p = fmaf(x2, p, -8.60467152213735e-11f);
    p = fmaf(x2, p, 5.12229709037114e-08f);
    p = fmaf(x2, p, 1.48572235717979e-05f);
    p = fmaf(x2, p, 6.37261928875436e-04f);
    p = fmaf(x2, p, 4.89352455891786e-03f);
    p *= xc;
    float q = fmaf(x2, 1.19825839466702e-06f, 1.18534705686654e-04f);
    q = fmaf(x2, q, 2.26843463243900e-03f);
    q = fmaf(x2, q, 4.89352518554385e-03f);
    return p * rcp_approx(q);
}
__device__ __forceinline__ float sigm_poly(float x) {
    return fmaf(0.5f, tanh_poly(0.5f * x), 0.5f);
}

// ---------------- fused prep: pack x, transpose w_ih, init h/c ---------------

__global__ __launch_bounds__(256) void prep_kernel(const float* __restrict__ lstm_in,
                                                   const float* __restrict__ init_i,
                                                   const float* __restrict__ w_ih,
                                                   const float* __restrict__ init_h,
                                                   const float* __restrict__ init_c) {
    __shared__ float tile[32][33];
    const int bid = blockIdx.x;
    const int tid = threadIdx.x;
    if (bid < 512) {
        int gid  = bid * 256 + tid;      // 131072 float4s
        int fidx = gid * 4;
        int row  = fidx >> 9;            // t*16 + b
        int d    = fidx & 511;
        int t = row >> 4, b = row & 15;
        float4 v;
        if (t == 0) v = *(const float4*)&init_i[d];
        else        v = *(const float4*)&lstm_in[(size_t)(b * 63 + (t - 1)) * 512 + d];
        *(float4*)&g_xcat[fidx] = v;
    } else if (bid < 1536) {
        int id = bid - 512;
        int cb = (id & 15) * 32;
        int rb = (id >> 4) * 32;
        int tx = tid & 31, ty = tid >> 5;
#pragma unroll
        for (int i = 0; i < 4; i++)
            tile[ty + i * 8][tx] = w_ih[(size_t)(rb + ty + i * 8) * 512 + cb + tx];
        __syncthreads();
#pragma unroll
        for (int i = 0; i < 4; i++)
            g_wihT[(size_t)(cb + ty + i * 8) * 2048 + rb + tx] = tile[tx][ty + i * 8];
    } else {
        int gid = (bid - 1536) * 256 + tid;   // 8192 entries
        int k = gid >> 4, b = gid & 15;
        g_h[k * 16 + b] = init_h[k];
        g_c[k * 16 + b] = init_c[k];
    }
}

// ---------------- f32x2 GEMM body: 256 threads, tile 128x128, 8x8/thread -----
// Per-output k-chain identical to the validated 128-thread body -> C is
// bit-identical; only block shape changes (2x warps/SM).

__device__ __forceinline__ void gemm_body256(const float* __restrict__ A,
                                             const float* __restrict__ B,
                                             float* __restrict__ C,
                                             int N, int K, int m0, int n0,
                                             float (*As)[132], float (*Bs)[128]) {
    const int tid = threadIdx.x;
    const int tx = tid & 15;          // n-dir (16 x 8 = 128)
    const int ty = tid >> 4;          // m-dir (16 x 8 = 128)

    unsigned long long acc[8][4];
#pragma unroll
    for (int i = 0; i < 8; i++)
#pragma unroll
        for (int p = 0; p < 4; p++) acc[i][p] = 0ull;

    float4 ra[2], rb[2];
#pragma unroll
    for (int l = 0; l < 2; l++) {
        int e = tid + l * 256;                   // 512 float4s
        int row = e >> 2, kq = e & 3;
        ra[l] = *(const float4*)&A[(size_t)(m0 + row) * K + kq * 4];
        int kr = e >> 5, nq = e & 31;
        rb[l] = *(const float4*)&B[(size_t)kr * N + n0 + nq * 4];
    }

    for (int k0 = 0; k0 < K; k0 += 16) {
#pragma unroll
        for (int l = 0; l < 2; l++) {
            int e = tid + l * 256;
            int row = e >> 2, kq = e & 3;
            As[kq * 4 + 0][row] = ra[l].x;
            As[kq * 4 + 1][row] = ra[l].y;
            As[kq * 4 + 2][row] = ra[l].z;
            As[kq * 4 + 3][row] = ra[l].w;
            int kr = e >> 5, nq = e & 31;
            *(float4*)&Bs[kr][nq * 4] = rb[l];
        }
        __syncthreads();
        if (k0 + 16 < K) {
#pragma unroll
            for (int l = 0; l < 2; l++) {
                int e = tid + l * 256;
                int row = e >> 2, kq = e & 3;
                ra[l] = *(const float4*)&A[(size_t)(m0 + row) * K + k0 + 16 + kq * 4];
                int kr = e >> 5, nq = e & 31;
                rb[l] = *(const float4*)&B[(size_t)(k0 + 16 + kr) * N + n0 + nq * 4];
            }
        }
#pragma unroll
        for (int k = 0; k < 16; k++) {
            float4 a0 = *(const float4*)&As[k][ty * 8];
            float4 a1 = *(const float4*)&As[k][ty * 8 + 4];
            ulonglong2 blo = *(const ulonglong2*)&Bs[k][tx * 4];
            ulonglong2 bhi = *(const ulonglong2*)&Bs[k][64 + tx * 4];
            float am[8] = {a0.x, a0.y, a0.z, a0.w, a1.x, a1.y, a1.z, a1.w};
#pragma unroll
            for (int i = 0; i < 8; i++) {
                unsigned long long pa = pk2(am[i]);
                fma2(acc[i][0], pa, blo.x);
                fma2(acc[i][1], pa, blo.y);
                fma2(acc[i][2], pa, bhi.x);
                fma2(acc[i][3], pa, bhi.y);
            }
        }
        __syncthreads();
    }
#pragma unroll
    for (int i = 0; i < 8; i++) {
        float* crow = C + (size_t)(m0 + ty * 8 + i) * N;
#pragma unroll
        for (int g = 0; g < 2; g++) {
#pragma unroll
            for (int p = 0; p < 2; p++) {
                int n = n0 + g * 64 + tx * 4 + p * 2;
                float lo, hi;
                unpk(acc[i][g * 2 + p], lo, hi);
                crow[n]     = lo;
                crow[n + 1] = hi;
            }
        }
    }
}

// merged: blocks 0..127 -> xg (1024x2048x512), 128..255 -> feat (4096x512x512)
__global__ __launch_bounds__(256) void gemm_merged_kernel(const float* __restrict__ xcat,
                                                          const float* __restrict__ wihT,
                                                          float* __restrict__ xg,
                                                          const float* __restrict__ ks,
                                                          const float* __restrict__ wm,
                                                          float* __restrict__ feat) {
    __shared__ float As[16][132];
    __shared__ float Bs[16][128];
    cudaGridDependencySynchronize();
    const int bid = blockIdx.x;
    if (bid < 128) {
        int bx = bid & 15, by = bid >> 4;     // n: 16x128, m: 8x128
        gemm_body256(xcat, wihT, xg, 2048, 512, by * 128, bx * 128, As, Bs);
    } else {
        int id = bid - 128;
        int bx = id & 3, by = id >> 2;        // n: 4x128, m: 32x128
        gemm_body256(ks, wm, feat, 512, 512, by * 128, bx * 128, As, Bs);
    }
    cudaTriggerProgrammaticLaunchCompletion();
}

// single GEMM (q = ys @ wq): grid (4, 8)
__global__ __launch_bounds__(256) void gemm_single_kernel(const float* __restrict__ A,
                                                          const float* __restrict__ B,
                                                          float* __restrict__ C,
                                                          int N, int K) {
    __shared__ float As[16][132];
    __shared__ float Bs[16][128];
    cudaGridDependencySynchronize();
    gemm_body256(A, B, C, N, K, blockIdx.y * 128, blockIdx.x * 128, As, Bs);
    cudaTriggerProgrammaticLaunchCompletion();
}

// ---------------- LSTM single step -------------------------------------------
// 128 blocks x 256 threads; block owns h-indices hb..hb+3 (16 gate rows).
// Staging (h,w -> smem) identical to R15/R16. Dot: thread = (rq=gate, bq,
// kc); 4x4 register tile; k = kc*4 + q*64 (16 kc-lanes read contiguous 256B
// per LDS -> conflict-free). kc-reduction: 16-lane f32x2 butterfly shuffle;
// lane kc writes slot (i,j) = (kc>>2, kc&3).

extern __shared__ float s_dyn[];   // [0:16*516) hs | [16*516:2*16*516) ws

__global__ __launch_bounds__(256) void lstm_step_kernel(int t,
                                                        const float* __restrict__ w_hh,
                                                        const float* __restrict__ b_ih,
                                                        const float* __restrict__ b_hh) {
    __shared__ float gsm[16][17];   // [lr = gate*4+off][b]
    float* hs = s_dyn;              // [b][k], stride 516
    float* ws = s_dyn + 16 * 516;   // [lr][k], stride 516

    const int tid = threadIdx.x;
    const int hb  = blockIdx.x * 4;
    const int rq  = tid >> 6;          // gate 0..3
    const int bq  = (tid >> 4) & 3;    // batch quad 0..3
    const int kc  = tid & 15;          // lane chunk 0..15

    // writer slot for this thread after reduction: (lr, b)
    const int iw = kc >> 2, jw = kc & 3;
    const int groww = rq * 512 + hb + iw;           // gate rq, offset iw
    const int bw = bq * 4 + jw;
    const float xgw = g_xg[t * 32768 + bw * 2048 + groww];
    const float bsw = b_ih[groww] + b_hh[groww];

    // staging indices (same as validated R15)
    int widx[8], wrow[8];
#pragma unroll
    for (int i = 0; i < 8; i++) {
        int e = tid + i * 256;          // 0..2047 float4s
        wrow[i] = e >> 7;               // local row 0..15
        widx[i] = e & 127;              // float4 within row
    }

    cudaGridDependencySynchronize();

    const float* hp = g_h + (t & 1) * 8192;
#pragma unroll
    for (int i = 0; i < 8; i++) {
        int idx = tid + i * 256;        // 2048 float4s
        int k = idx >> 2, bqq = (idx & 3) * 4;
        float4 v = ldcg4(hp + idx * 4);
        hs[(bqq + 0) * 516 + k] = v.x;
        hs[(bqq + 1) * 516 + k] = v.y;
        hs[(bqq + 2) * 516 + k] = v.z;
        hs[(bqq + 3) * 516 + k] = v.w;
    }
#pragma unroll
    for (int i = 0; i < 8; i++) {
        int lr = wrow[i];
        int gr = (lr >> 2) * 512 + hb + (lr & 3);
        float4 v = ldcg4(&w_hh[(size_t)gr * 512 + widx[i] * 4]);
        *(float4*)&ws[lr * 516 + widx[i] * 4] = v;
    }
    __syncthreads();

    cudaTriggerProgrammaticLaunchCompletion();

    // 4x4 register-tiled dot (gate rq rows rq*4+i; batches bq*4+j)
    const float* wr0 = ws + (rq * 4 + 0) * 516;
    const float* wr1 = ws + (rq * 4 + 1) * 516;
    const float* wr2 = ws + (rq * 4 + 2) * 516;
    const float* wr3 = ws + (rq * 4 + 3) * 516;
    const float* hr0 = hs + (bq * 4 + 0) * 516;
    const float* hr1 = hs + (bq * 4 + 1) * 516;
    const float* hr2 = hs + (bq * 4 + 2) * 516;
    const float* hr3 = hs + (bq * 4 + 3) * 516;

    unsigned long long acc[4][4];
#pragma unroll
    for (int i = 0; i < 4; i++)
#pragma unroll
        for (int j = 0; j < 4; j++) acc[i][j] = 0ull;

#pragma unroll
    for (int q = 0; q < 8; q++) {
        const int k = kc * 4 + q * 64;
        ulonglong2 wv[4], hv[4];
        wv[0] = *(const ulonglong2*)(wr0 + k);
        wv[1] = *(const ulonglong2*)(wr1 + k);
        wv[2] = *(const ulonglong2*)(wr2 + k);
        wv[3] = *(const ulonglong2*)(wr3 + k);
        hv[0] = *(const ulonglong2*)(hr0 + k);
        hv[1] = *(const ulonglong2*)(hr1 + k);
        hv[2] = *(const ulonglong2*)(hr2 + k);
        hv[3] = *(const ulonglong2*)(hr3 + k);
#pragma unroll
        for (int i = 0; i < 4; i++)
#pragma unroll
            for (int j = 0; j < 4; j++) {
                fma2(acc[i][j], wv[i].x, hv[j].x);
                fma2(acc[i][j], wv[i].y, hv[j].y);
            }
    }

    // butterfly-reduce across the 16 kc lanes (packed f32x2, fixed order)
#pragma unroll
    for (int i = 0; i < 4; i++)
#pragma unroll
        for (int j = 0; j < 4; j++) {
#pragma unroll
            for (int m = 1; m < 16; m <<= 1) {
                unsigned long long o =
                    __shfl_xor_sync(0xffffffffu, acc[i][j], m);
                acc[i][j] = add2(acc[i][j], o);
            }
        }

    // lane kc writes slot (iw, jw)
#pragma unroll
    for (int i = 0; i < 4; i++)
#pragma unroll
        for (int j = 0; j < 4; j++)
            if (iw == i && jw == j)
                gsm[rq * 4 + i][bq * 4 + j] = (xgw + upsum(acc[i][j])) + bsw;
    __syncthreads();

    // cell tail (validated)
    if (tid < 64) {
        int jj = tid >> 4, bb = tid & 15;
        float gi = sigm_poly(gsm[jj][bb]);        // gate i
        float gf = sigm_poly(gsm[4 + jj][bb]);    // gate f
        float gg = tanh_poly(gsm[8 + jj][bb]);    // gate g
        float go = sigm_poly(gsm[12 + jj][bb]);   // gate o
        int ci = (hb + jj) * 16 + bb;
        float c = gf * g_c[ci] + gi * gg;
        g_c[ci] = c;
        float h = go * tanh_poly(c);
        g_h[((t + 1) & 1) * 8192 + ci] = h;
        g_ys[(size_t)((bb << 6) + t) * 512 + hb + jj] = h;
    }
}

// ---------------- score: out[b][t][m] = sum_h tanh(feat+q) * v --------------

__global__ __launch_bounds__(128) void score_kernel(const float* __restrict__ v,
                                                    float* __restrict__ out) {
    cudaGridDependencySynchronize();
    const int b  = blockIdx.y, mg = blockIdx.x;       // mg 0..31
    const int w  = threadIdx.x >> 5, lane = threadIdx.x & 31;
    const int m0 = mg * 8 + w * 2;
    const float* fp0 = g_feat + (size_t)((b << 8) + m0) * 512;
    const float* fp1 = fp0 + 512;

    float4 ff0[4], ff1[4], vv[4];
#pragma unroll
    for (int j = 0; j < 4; j++) {
        ff0[j] = *(const float4*)&fp0[lane * 4 + j * 128];
        ff1[j] = *(const float4*)&fp1[lane * 4 + j * 128];
        vv[j]  = *(const float4*)&v[lane * 4 + j * 128];
    }
    for (int t = 0; t < 64; t++) {
        const float* qp = g_q + (size_t)((b << 6) + t) * 512;
        float s0 = 0.0f, s1 = 0.0f;
#pragma unroll
        for (int j = 0; j < 4; j++) {
            float4 qv = __ldg((const float4*)&qp[lane * 4 + j * 128]);
            s0 += tanh_hw(ff0[j].x + qv.x) * vv[j].x;
            s0 += tanh_hw(ff0[j].y + qv.y) * vv[j].y;
            s0 += tanh_hw(ff0[j].z + qv.z) * vv[j].z;
            s0 += tanh_hw(ff0[j].w + qv.w) * vv[j].w;
            s1 += tanh_hw(ff1[j].x + qv.x) * vv[j].x;
            s1 += tanh_hw(ff1[j].y + qv.y) * vv[j].y;
            s1 += tanh_hw(ff1[j].z + qv.z) * vv[j].z;
            s1 += tanh_hw(ff1[j].w + qv.w) * vv[j].w;
        }
#pragma unroll
        for (int off = 16; off; off >>= 1) {
            s0 += __shfl_xor_sync(0xffffffffu, s0, off);
            s1 += __shfl_xor_sync(0xffffffffu, s1, off);
        }
        if (lane == 0) {
            float* orow = out + (size_t)((b << 6) + t) * 256;
            orow[m0]     = s0;
            orow[m0 + 1] = s1;
        }
    }
}

// ---------------- PDL launch helper -----------------------------------------

template <typename F, typename... Args>
static inline void launch_pdl(F f, dim3 grid, dim3 block, size_t smem, Args... args) {
    cudaLaunchConfig_t cfg = {};
    cfg.gridDim = grid;
    cfg.blockDim = block;
    cfg.dynamicSmemBytes = smem;
    cfg.stream = 0;
    cudaLaunchAttribute attr[1];
    attr[0].id = cudaLaunchAttributeProgrammaticStreamSerialization;
    attr[0].val.programmaticStreamSerializationAllowed = 1;
    cfg.attrs = attr;
    cfg.numAttrs = 1;
    cudaLaunchKernelEx(&cfg, f, args...);
}

// ---------------- launch ----------------------------------------------------

extern "C" void kernel_launch(void* const* d_in, const int* in_sizes, int n_in,
                              void* d_out, int out_size) {
    const int o = (n_in == 12) ? 1 : 0;
    const float* ks      = (const float*)d_in[0];
    const float* lstm_in = (const float*)d_in[2 - o];
    const float* init_h  = (const float*)d_in[3 - o];
    const float* init_c  = (const float*)d_in[4 - o];
    const float* init_i  = (const float*)d_in[5 - o];
    const float* w_ih    = (const float*)d_in[6 - o];
    const float* w_hh    = (const float*)d_in[7 - o];
    const float* b_ih    = (const float*)d_in[8 - o];
    const float* b_hh    = (const float*)d_in[9 - o];
    const float* attn_wm = (const float*)d_in[10 - o];
    const float* attn_wq = (const float*)d_in[11 - o];
    const float* attn_v  = (const float*)d_in[12 - o];
    float* out = (float*)d_out;

    void *p_xcat, *p_wihT, *p_xg, *p_feat, *p_ys, *p_q;
    cudaGetSymbolAddress(&p_xcat, g_xcat);
    cudaGetSymbolAddress(&p_wihT, g_wihT);
    cudaGetSymbolAddress(&p_xg,   g_xg);
    cudaGetSymbolAddress(&p_feat, g_feat);
    cudaGetSymbolAddress(&p_ys,   g_ys);
    cudaGetSymbolAddress(&p_q,    g_q);

    const size_t lstm_smem = 2 * 16 * 516 * sizeof(float);   // 66048 B
    cudaFuncSetAttribute(lstm_step_kernel,
                         cudaFuncAttributeMaxDynamicSharedMemorySize,
                         (int)lstm_smem);

    // 1) fused prep
    prep_kernel<<<1568, 256>>>(lstm_in, init_i, w_ih, init_h, init_c);

    // 2+3) merged GEMM (256 blocks x 256 threads)
    launch_pdl(gemm_merged_kernel, dim3(256), dim3(256), 0,
               (const float*)p_xcat, (const float*)p_wihT, (float*)p_xg,
               ks, attn_wm, (float*)p_feat);

    // 4) LSTM: 64 step launches
    for (int t = 0; t < 64; t++)
        launch_pdl(lstm_step_kernel, dim3(128), dim3(256), lstm_smem,
                   t, w_hh, b_ih, b_hh);

    // 5) q = ys @ attn_wq  [1024 x 512]
    launch_pdl(gemm_single_kernel, dim3(4, 8), dim3(256), 0,
               (const float*)p_ys, attn_wq, (float*)p_q, 512, 512);

    // 6) score
    launch_pdl(score_kernel, dim3(32, 16), dim3(128), 0, attn_v, out);
}